// round 2
// baseline (speedup 1.0000x reference)
#include <cuda_runtime.h>
#include <cstdint>
#include <cstddef>

// GroupedLinearsAdvanced: out[b,o,d] = sum_i x[b,i,d] * W[d,i,o] + bias[d,o]
//   x:    [16, 128, 4096] fp32
//   W:    [4096, 128, 128] fp32   (256 MB, streamed once -> HBM bound)
//   bias: [4096, 128] fp32
//   out:  [16, 128, 4096] fp32
//
// One CTA handles 8 consecutive d-channels. Warp w owns d = d0 + w and
// streams W_d (64 KB) from GMEM with __ldcs. x tile lives in smem laid out
// [i][dd][b] so compute reads are warp-broadcast LDS.128 and b-pairs are
// pre-packed for fma.rn.f32x2. Output is transposed through smem so global
// stores are 32B d-contiguous runs (full sectors).

#define B_SZ     16
#define IN_D     128
#define OUT_D    128
#define D_TOT    4096
#define D_TILE   8
#define XS_STRIDE 136                      // floats per i-row: 8*16 + 8 pad
#define SMEM_FLOATS (IN_D * XS_STRIDE)     // 17408 floats = 69632 B
#define SMEM_BYTES  (SMEM_FLOATS * 4)

__global__ void __launch_bounds__(256, 2)
grouped_linears_kernel(const float* __restrict__ x,
                       const float* __restrict__ W,
                       const float* __restrict__ bias,
                       float* __restrict__ out)
{
    extern __shared__ float sm[];   // phase 1: x tile   phase 2: out transpose

    const int tid  = threadIdx.x;
    const int warp = tid >> 5;
    const int lane = tid & 31;
    const int d0   = blockIdx.x * D_TILE;
    const int d    = d0 + warp;

    // ---------------- Phase 0: load x tile ----------------
    // sm[i*XS_STRIDE + dd*16 + b] = x[b][i][d0+dd]
    // p = i*16 + b ordering: warp lanes vary b fast -> <=2-way bank conflict on scatter.
#pragma unroll
    for (int r = 0; r < 8; ++r) {
        int p = tid + r * 256;          // 0..2047
        int i = p >> 4;
        int b = p & 15;
        const float4* gp =
            reinterpret_cast<const float4*>(x + ((size_t)b * IN_D + i) * D_TOT + d0);
        float4 v0 = gp[0];
        float4 v1 = gp[1];
        float* row = &sm[i * XS_STRIDE + b];
        row[0 * 16] = v0.x; row[1 * 16] = v0.y; row[2 * 16] = v0.z; row[3 * 16] = v0.w;
        row[4 * 16] = v1.x; row[5 * 16] = v1.y; row[6 * 16] = v1.z; row[7 * 16] = v1.w;
    }
    __syncthreads();

    // ---------------- Phase 1: main GEMM loop ----------------
    // acc2[k][j]: packed f32x2 accumulator for (b=2k lo, b=2k+1 hi), o = 4*lane + j.
    unsigned long long acc2[8][4];
    {
        float4 bv = *reinterpret_cast<const float4*>(bias + (size_t)d * OUT_D + 4 * lane);
        float bj[4] = {bv.x, bv.y, bv.z, bv.w};
#pragma unroll
        for (int j = 0; j < 4; ++j) {
            unsigned long long pk;
            asm("mov.b64 %0, {%1, %1};" : "=l"(pk) : "f"(bj[j]));
#pragma unroll
            for (int k = 0; k < 8; ++k) acc2[k][j] = pk;
        }
    }

    // W[d][i][4*lane] as float4; each i advances 128 floats = 32 float4
    const float4* wp = reinterpret_cast<const float4*>(W + (size_t)d * IN_D * OUT_D) + lane;
    float4 wcur = __ldcs(wp);

#pragma unroll 4
    for (int i = 0; i < IN_D; ++i) {
        int inext = (i + 1 < IN_D) ? (i + 1) : (IN_D - 1);
        float4 wnext = __ldcs(wp + inext * 32);   // 1-deep prefetch

        // x pairs for this (i, d): 16 floats = 4x LDS.128, all lanes broadcast
        const double2* xr =
            reinterpret_cast<const double2*>(&sm[i * XS_STRIDE + warp * 16]);
        double2 a0 = xr[0], a1 = xr[1], a2 = xr[2], a3 = xr[3];
        unsigned long long x2[8];
        x2[0] = __double_as_longlong(a0.x); x2[1] = __double_as_longlong(a0.y);
        x2[2] = __double_as_longlong(a1.x); x2[3] = __double_as_longlong(a1.y);
        x2[4] = __double_as_longlong(a2.x); x2[5] = __double_as_longlong(a2.y);
        x2[6] = __double_as_longlong(a3.x); x2[7] = __double_as_longlong(a3.y);

        // duplicate W scalars into both f32x2 halves
        unsigned long long wd[4];
        asm("mov.b64 %0, {%1, %1};" : "=l"(wd[0]) : "f"(wcur.x));
        asm("mov.b64 %0, {%1, %1};" : "=l"(wd[1]) : "f"(wcur.y));
        asm("mov.b64 %0, {%1, %1};" : "=l"(wd[2]) : "f"(wcur.z));
        asm("mov.b64 %0, {%1, %1};" : "=l"(wd[3]) : "f"(wcur.w));

#pragma unroll
        for (int k = 0; k < 8; ++k) {
#pragma unroll
            for (int j = 0; j < 4; ++j) {
                asm("fma.rn.f32x2 %0, %1, %2, %0;"
                    : "+l"(acc2[k][j]) : "l"(x2[k]), "l"(wd[j]));
            }
        }
        wcur = wnext;
    }

    // ---------------- Phase 2: transpose through smem ----------------
    __syncthreads();   // done reading x tile
    // outs[dd][b*128 + o], dd = warp
    float* outs = sm;
#pragma unroll
    for (int k = 0; k < 8; ++k) {
#pragma unroll
        for (int j = 0; j < 4; ++j) {
            float lo, hi;
            asm("mov.b64 {%0, %1}, %2;" : "=f"(lo), "=f"(hi) : "l"(acc2[k][j]));
            int o = 4 * lane + j;
            outs[warp * 2048 + (2 * k)     * 128 + o] = lo;
            outs[warp * 2048 + (2 * k + 1) * 128 + o] = hi;
        }
    }
    __syncthreads();

    // ---------------- Phase 3: coalesced global store ----------------
    // Each (b,o) pair p gets an 8-float d-contiguous run: two float4 stores
    // into the same 32B-aligned region.
#pragma unroll
    for (int r = 0; r < 2; ++r) {
        int p4 = 4 * (tid + r * 256);   // groups of 4 consecutive p
        float v[8][4];
#pragma unroll
        for (int dd = 0; dd < 8; ++dd) {
            float4 t4 = *reinterpret_cast<float4*>(&outs[dd * 2048 + p4]);
            v[dd][0] = t4.x; v[dd][1] = t4.y; v[dd][2] = t4.z; v[dd][3] = t4.w;
        }
#pragma unroll
        for (int pp = 0; pp < 4; ++pp) {
            int p = p4 + pp;            // p = b*128 + o
            float* op = out + (size_t)p * D_TOT + d0;
            float4 lo4 = make_float4(v[0][pp], v[1][pp], v[2][pp], v[3][pp]);
            float4 hi4 = make_float4(v[4][pp], v[5][pp], v[6][pp], v[7][pp]);
            *reinterpret_cast<float4*>(op)     = lo4;
            *reinterpret_cast<float4*>(op + 4) = hi4;
        }
    }
}

extern "C" void kernel_launch(void* const* d_in, const int* in_sizes, int n_in,
                              void* d_out, int out_size)
{
    (void)in_sizes; (void)n_in; (void)out_size;
    const float* x    = (const float*)d_in[0];
    const float* W    = (const float*)d_in[1];
    const float* bias = (const float*)d_in[2];
    float*       out  = (float*)d_out;

    // Idempotent, host-side, not a stream op: safe under graph capture.
    cudaFuncSetAttribute(grouped_linears_kernel,
                         cudaFuncAttributeMaxDynamicSharedMemorySize, SMEM_BYTES);

    grouped_linears_kernel<<<D_TOT / D_TILE, 256, SMEM_BYTES>>>(x, W, bias, out);
}

// round 4
// speedup vs baseline: 1.0532x; 1.0532x over previous
#include <cuda_runtime.h>
#include <cstdint>
#include <cstddef>

// GroupedLinearsAdvanced: out[b,o,d] = sum_i x[b,i,d] * W[d,i,o] + bias[d,o]
//   x:    [16, 128, 4096] fp32
//   W:    [4096, 128, 128] fp32   (256 MB, streamed once -> HBM bound)
//   bias: [4096, 128] fp32
//   out:  [16, 128, 4096] fp32
//
// R2 -> R3 change: W stream now uses a 4-deep software-pipelined prefetch
// (rolling float4 buffer) instead of 1-deep. Per-SM bytes in flight rise
// from ~8-16KB to ~32KB, crossing the Little's-law threshold (~21KB) for
// saturating the per-SM DRAM bandwidth share. Everything else unchanged.

#define B_SZ     16
#define IN_D     128
#define OUT_D    128
#define D_TOT    4096
#define D_TILE   8
#define PF_DEPTH 4
#define XS_STRIDE 136                      // floats per i-row: 8*16 + 8 pad
#define SMEM_FLOATS (IN_D * XS_STRIDE)     // 17408 floats = 69632 B
#define SMEM_BYTES  (SMEM_FLOATS * 4)

__global__ void __launch_bounds__(256, 2)
grouped_linears_kernel(const float* __restrict__ x,
                       const float* __restrict__ W,
                       const float* __restrict__ bias,
                       float* __restrict__ out)
{
    extern __shared__ float sm[];   // phase 1: x tile   phase 2: out transpose

    const int tid  = threadIdx.x;
    const int warp = tid >> 5;
    const int lane = tid & 31;
    const int d0   = blockIdx.x * D_TILE;
    const int d    = d0 + warp;

    // ---------------- Phase 0: load x tile ----------------
    // sm[i*XS_STRIDE + dd*16 + b] = x[b][i][d0+dd]
#pragma unroll
    for (int r = 0; r < 8; ++r) {
        int p = tid + r * 256;          // 0..2047
        int i = p >> 4;
        int b = p & 15;
        const float4* gp =
            reinterpret_cast<const float4*>(x + ((size_t)b * IN_D + i) * D_TOT + d0);
        float4 v0 = gp[0];
        float4 v1 = gp[1];
        float* row = &sm[i * XS_STRIDE + b];
        row[0 * 16] = v0.x; row[1 * 16] = v0.y; row[2 * 16] = v0.z; row[3 * 16] = v0.w;
        row[4 * 16] = v1.x; row[5 * 16] = v1.y; row[6 * 16] = v1.z; row[7 * 16] = v1.w;
    }

    // W[d][i][4*lane] as float4; each i advances 128 floats = 32 float4.
    // Kick off the 4-deep prefetch BEFORE the barrier so the first W loads
    // overlap the x-tile staging of other warps.
    const float4* wp = reinterpret_cast<const float4*>(W + (size_t)d * IN_D * OUT_D) + lane;
    float4 wbuf[PF_DEPTH];
#pragma unroll
    for (int s = 0; s < PF_DEPTH; ++s) wbuf[s] = __ldcs(wp + s * 32);

    __syncthreads();

    // ---------------- Phase 1: main GEMM loop ----------------
    // acc2[k][j]: packed f32x2 accumulator for (b=2k lo, b=2k+1 hi), o = 4*lane + j.
    unsigned long long acc2[8][4];
    {
        float4 bv = *reinterpret_cast<const float4*>(bias + (size_t)d * OUT_D + 4 * lane);
        float bj[4] = {bv.x, bv.y, bv.z, bv.w};
#pragma unroll
        for (int j = 0; j < 4; ++j) {
            unsigned long long pk;
            asm("mov.b64 %0, {%1, %1};" : "=l"(pk) : "f"(bj[j]));
#pragma unroll
            for (int k = 0; k < 8; ++k) acc2[k][j] = pk;
        }
    }

#pragma unroll 4
    for (int i = 0; i < IN_D; ++i) {
        // consume slot, immediately re-fill it 4 iterations ahead
        float4 wcur = wbuf[i & (PF_DEPTH - 1)];
        int ipf = i + PF_DEPTH;
        if (ipf < IN_D) wbuf[i & (PF_DEPTH - 1)] = __ldcs(wp + ipf * 32);

        // x pairs for this (i, d): 16 floats = 4x LDS.128, all lanes broadcast
        const double2* xr =
            reinterpret_cast<const double2*>(&sm[i * XS_STRIDE + warp * 16]);
        double2 a0 = xr[0], a1 = xr[1], a2 = xr[2], a3 = xr[3];
        unsigned long long x2[8];
        x2[0] = __double_as_longlong(a0.x); x2[1] = __double_as_longlong(a0.y);
        x2[2] = __double_as_longlong(a1.x); x2[3] = __double_as_longlong(a1.y);
        x2[4] = __double_as_longlong(a2.x); x2[5] = __double_as_longlong(a2.y);
        x2[6] = __double_as_longlong(a3.x); x2[7] = __double_as_longlong(a3.y);

        // duplicate W scalars into both f32x2 halves
        unsigned long long wd[4];
        asm("mov.b64 %0, {%1, %1};" : "=l"(wd[0]) : "f"(wcur.x));
        asm("mov.b64 %0, {%1, %1};" : "=l"(wd[1]) : "f"(wcur.y));
        asm("mov.b64 %0, {%1, %1};" : "=l"(wd[2]) : "f"(wcur.z));
        asm("mov.b64 %0, {%1, %1};" : "=l"(wd[3]) : "f"(wcur.w));

#pragma unroll
        for (int k = 0; k < 8; ++k) {
#pragma unroll
            for (int j = 0; j < 4; ++j) {
                asm("fma.rn.f32x2 %0, %1, %2, %0;"
                    : "+l"(acc2[k][j]) : "l"(x2[k]), "l"(wd[j]));
            }
        }
    }

    // ---------------- Phase 2: transpose through smem ----------------
    __syncthreads();   // done reading x tile
    // outs[dd][b*128 + o], dd = warp
    float* outs = sm;
#pragma unroll
    for (int k = 0; k < 8; ++k) {
#pragma unroll
        for (int j = 0; j < 4; ++j) {
            float lo, hi;
            asm("mov.b64 {%0, %1}, %2;" : "=f"(lo), "=f"(hi) : "l"(acc2[k][j]));
            int o = 4 * lane + j;
            outs[warp * 2048 + (2 * k)     * 128 + o] = lo;
            outs[warp * 2048 + (2 * k + 1) * 128 + o] = hi;
        }
    }
    __syncthreads();

    // ---------------- Phase 3: coalesced global store ----------------
    // Each (b,o) pair p gets an 8-float d-contiguous run: two float4 stores
    // into the same 32B-aligned region.
#pragma unroll
    for (int r = 0; r < 2; ++r) {
        int p4 = 4 * (tid + r * 256);   // groups of 4 consecutive p
        float v[8][4];
#pragma unroll
        for (int dd = 0; dd < 8; ++dd) {
            float4 t4 = *reinterpret_cast<float4*>(&outs[dd * 2048 + p4]);
            v[dd][0] = t4.x; v[dd][1] = t4.y; v[dd][2] = t4.z; v[dd][3] = t4.w;
        }
#pragma unroll
        for (int pp = 0; pp < 4; ++pp) {
            int p = p4 + pp;            // p = b*128 + o
            float* op = out + (size_t)p * D_TOT + d0;
            float4 lo4 = make_float4(v[0][pp], v[1][pp], v[2][pp], v[3][pp]);
            float4 hi4 = make_float4(v[4][pp], v[5][pp], v[6][pp], v[7][pp]);
            *reinterpret_cast<float4*>(op)     = lo4;
            *reinterpret_cast<float4*>(op + 4) = hi4;
        }
    }
}

extern "C" void kernel_launch(void* const* d_in, const int* in_sizes, int n_in,
                              void* d_out, int out_size)
{
    (void)in_sizes; (void)n_in; (void)out_size;
    const float* x    = (const float*)d_in[0];
    const float* W    = (const float*)d_in[1];
    const float* bias = (const float*)d_in[2];
    float*       out  = (float*)d_out;

    // Idempotent, host-side, not a stream op: safe under graph capture.
    cudaFuncSetAttribute(grouped_linears_kernel,
                         cudaFuncAttributeMaxDynamicSharedMemorySize, SMEM_BYTES);

    grouped_linears_kernel<<<D_TOT / D_TILE, 256, SMEM_BYTES>>>(x, W, bias, out);
}

// round 6
// speedup vs baseline: 1.1472x; 1.0892x over previous
#include <cuda_runtime.h>
#include <cstdint>
#include <cstddef>

// GroupedLinearsAdvanced: out[b,o,d] = sum_i x[b,i,d] * W[d,i,o] + bias[d,o]
//   x:    [16, 128, 4096] fp32
//   W:    [4096, 128, 128] fp32   (256 MB, streamed once -> HBM bound)
//   bias: [4096, 128] fp32
//   out:  [16, 128, 4096] fp32
//
// R5: quarter-size CTAs. D_TILE 8->4, 128 threads, grid 1024, 4 CTAs/SM.
// Same inner loop (at its FMA-pipe floor) and same per-warp W stream, but
// per-SM tail imbalance drops from ~15% to ~1% and the serial per-CTA
// phases (x load / store drain) are overlapped by 3 sibling CTAs.

#define B_SZ     16
#define IN_D     128
#define OUT_D    128
#define D_TOT    4096
#define D_TILE   4
#define THREADS  128
#define PF_DEPTH 4
#define XS_STRIDE 72                       // floats per i-row: 4*16 + 8 pad
#define SMEM_FLOATS (IN_D * XS_STRIDE)     // 9216 floats = 36864 B
#define SMEM_BYTES  (SMEM_FLOATS * 4)

__global__ void __launch_bounds__(THREADS, 4)
grouped_linears_kernel(const float* __restrict__ x,
                       const float* __restrict__ W,
                       const float* __restrict__ bias,
                       float* __restrict__ out)
{
    extern __shared__ float sm[];   // phase 1: x tile   phase 2: out transpose

    const int tid  = threadIdx.x;
    const int warp = tid >> 5;      // 0..3, one d-channel per warp
    const int lane = tid & 31;
    const int d0   = blockIdx.x * D_TILE;
    const int d    = d0 + warp;

    // W[d][i][4*lane] as float4; each i advances 128 floats = 32 float4.
    // Kick the prefetch off FIRST so W is in flight during x staging.
    const float4* wp = reinterpret_cast<const float4*>(W + (size_t)d * IN_D * OUT_D) + lane;
    float4 wbuf[PF_DEPTH];
#pragma unroll
    for (int s = 0; s < PF_DEPTH; ++s) wbuf[s] = __ldcs(wp + s * 32);

    // bias early too
    float4 bv = *reinterpret_cast<const float4*>(bias + (size_t)d * OUT_D + 4 * lane);

    // ---------------- Phase 0: load x tile ----------------
    // sm[i*XS_STRIDE + dd*16 + b] = x[b][i][d0+dd]; 16 float4 per thread.
#pragma unroll
    for (int r = 0; r < 16; ++r) {
        int p = tid + r * THREADS;      // 0..2047
        int i = p >> 4;
        int b = p & 15;
        float4 v = *reinterpret_cast<const float4*>(
            x + ((size_t)b * IN_D + i) * D_TOT + d0);
        float* row = &sm[i * XS_STRIDE + b];
        row[0 * 16] = v.x; row[1 * 16] = v.y; row[2 * 16] = v.z; row[3 * 16] = v.w;
    }
    __syncthreads();

    // ---------------- Phase 1: main GEMM loop ----------------
    // acc2[k][j]: packed f32x2 accumulator for (b=2k lo, b=2k+1 hi), o = 4*lane + j.
    unsigned long long acc2[8][4];
    {
        float bj[4] = {bv.x, bv.y, bv.z, bv.w};
#pragma unroll
        for (int j = 0; j < 4; ++j) {
            unsigned long long pk;
            asm("mov.b64 %0, {%1, %1};" : "=l"(pk) : "f"(bj[j]));
#pragma unroll
            for (int k = 0; k < 8; ++k) acc2[k][j] = pk;
        }
    }

#pragma unroll 4
    for (int i = 0; i < IN_D; ++i) {
        // consume slot, immediately re-fill it PF_DEPTH iterations ahead
        float4 wcur = wbuf[i & (PF_DEPTH - 1)];
        int ipf = i + PF_DEPTH;
        if (ipf < IN_D) wbuf[i & (PF_DEPTH - 1)] = __ldcs(wp + ipf * 32);

        // x pairs for this (i, d): 16 floats = 4x LDS.128, all lanes broadcast
        const double2* xr =
            reinterpret_cast<const double2*>(&sm[i * XS_STRIDE + warp * 16]);
        double2 a0 = xr[0], a1 = xr[1], a2 = xr[2], a3 = xr[3];
        unsigned long long x2[8];
        x2[0] = __double_as_longlong(a0.x); x2[1] = __double_as_longlong(a0.y);
        x2[2] = __double_as_longlong(a1.x); x2[3] = __double_as_longlong(a1.y);
        x2[4] = __double_as_longlong(a2.x); x2[5] = __double_as_longlong(a2.y);
        x2[6] = __double_as_longlong(a3.x); x2[7] = __double_as_longlong(a3.y);

        // duplicate W scalars into both f32x2 halves
        unsigned long long wd[4];
        asm("mov.b64 %0, {%1, %1};" : "=l"(wd[0]) : "f"(wcur.x));
        asm("mov.b64 %0, {%1, %1};" : "=l"(wd[1]) : "f"(wcur.y));
        asm("mov.b64 %0, {%1, %1};" : "=l"(wd[2]) : "f"(wcur.z));
        asm("mov.b64 %0, {%1, %1};" : "=l"(wd[3]) : "f"(wcur.w));

#pragma unroll
        for (int k = 0; k < 8; ++k) {
#pragma unroll
            for (int j = 0; j < 4; ++j) {
                asm("fma.rn.f32x2 %0, %1, %2, %0;"
                    : "+l"(acc2[k][j]) : "l"(x2[k]), "l"(wd[j]));
            }
        }
    }

    // ---------------- Phase 2: transpose through smem ----------------
    __syncthreads();   // done reading x tile
    // outs[dd][b*128 + o], dd = warp (0..3)
    float* outs = sm;
#pragma unroll
    for (int k = 0; k < 8; ++k) {
#pragma unroll
        for (int j = 0; j < 4; ++j) {
            float lo, hi;
            asm("mov.b64 {%0, %1}, %2;" : "=f"(lo), "=f"(hi) : "l"(acc2[k][j]));
            int o = 4 * lane + j;
            outs[warp * 2048 + (2 * k)     * 128 + o] = lo;
            outs[warp * 2048 + (2 * k + 1) * 128 + o] = hi;
        }
    }
    __syncthreads();

    // ---------------- Phase 3: coalesced global store ----------------
    // Each (b,o) pair p gets a 4-float d-contiguous run (one float4; the
    // adjacent-d0 CTA fills the sector's other half, merged in L2).
#pragma unroll
    for (int r = 0; r < 4; ++r) {
        int p4 = 4 * (tid + r * THREADS);   // groups of 4 consecutive p
        float v[D_TILE][4];
#pragma unroll
        for (int dd = 0; dd < D_TILE; ++dd) {
            float4 t4 = *reinterpret_cast<float4*>(&outs[dd * 2048 + p4]);
            v[dd][0] = t4.x; v[dd][1] = t4.y; v[dd][2] = t4.z; v[dd][3] = t4.w;
        }
#pragma unroll
        for (int pp = 0; pp < 4; ++pp) {
            int p = p4 + pp;            // p = b*128 + o
            float* op = out + (size_t)p * D_TOT + d0;
            *reinterpret_cast<float4*>(op) =
                make_float4(v[0][pp], v[1][pp], v[2][pp], v[3][pp]);
        }
    }
}

extern "C" void kernel_launch(void* const* d_in, const int* in_sizes, int n_in,
                              void* d_out, int out_size)
{
    (void)in_sizes; (void)n_in; (void)out_size;
    const float* x    = (const float*)d_in[0];
    const float* W    = (const float*)d_in[1];
    const float* bias = (const float*)d_in[2];
    float*       out  = (float*)d_out;

    // Idempotent, host-side, not a stream op: safe under graph capture.
    cudaFuncSetAttribute(grouped_linears_kernel,
                         cudaFuncAttributeMaxDynamicSharedMemorySize, SMEM_BYTES);

    grouped_linears_kernel<<<D_TOT / D_TILE, THREADS, SMEM_BYTES>>>(x, W, bias, out);
}